// round 2
// baseline (speedup 1.0000x reference)
#include <cuda_runtime.h>
#include <stdint.h>

// Problem constants (fixed by setup_inputs): B=32, T=512, dur < 16.
#define B_SZ 32
#define T_SZ 512
#define M_MAX (T_SZ * 15)   // worst-case frames per row = 7680

// frame -> token map, -1 for padding frames. Scratch as __device__ global
// (no allocations allowed). 32 * 7680 * 4B ~= 3.9 MB.
__device__ int g_f2t[B_SZ * M_MAX];

// Kernel A: one block per batch row. Inclusive scan of durations, then each
// token scatters its index over its frame range. Frames >= total stay -1.
__global__ void __launch_bounds__(T_SZ) build_f2t_kernel(
    const int* __restrict__ dur, int M)
{
    __shared__ int s[T_SZ];
    const int b = blockIdx.x;
    const int t = threadIdx.x;

    const int d = dur[b * T_SZ + t];
    s[t] = d;
    __syncthreads();

    // Hillis-Steele inclusive scan over 512 elements.
    #pragma unroll
    for (int off = 1; off < T_SZ; off <<= 1) {
        int v = s[t];
        if (t >= off) v += s[t - off];
        __syncthreads();
        s[t] = v;
        __syncthreads();
    }

    const int end   = s[t];
    const int start = end - d;

    // Init this row's map to -1 (covers frames [total, M)).
    int* row = g_f2t + (size_t)b * M;
    for (int f = t; f < M; f += T_SZ) row[f] = -1;
    __syncthreads();

    // Scatter: token t owns frames [start, end). d <= 15.
    for (int f = start; f < end; f++) row[f] = t;
}

// Kernel B: one thread per float4 of the [B, M, T] output.
// row index (b*M + f) = idx >> 7 since T/4 = 128.
__global__ void __launch_bounds__(256) write_align_kernel(
    float4* __restrict__ out, long long n4)
{
    const long long idx = (long long)blockIdx.x * blockDim.x + threadIdx.x;
    if (idx >= n4) return;

    const long long row = idx >> 7;          // (b, f) flat index
    const int tok = __ldg(&g_f2t[row]);      // broadcast within the 128-thread row
    const int t0  = ((int)idx & 127) << 2;   // first token column of this float4

    float4 v;
    v.x = (t0     == tok) ? 1.0f : 0.0f;
    v.y = (t0 + 1 == tok) ? 1.0f : 0.0f;
    v.z = (t0 + 2 == tok) ? 1.0f : 0.0f;
    v.w = (t0 + 3 == tok) ? 1.0f : 0.0f;
    out[idx] = v;
}

extern "C" void kernel_launch(void* const* d_in, const int* in_sizes, int n_in,
                              void* d_out, int out_size)
{
    const int* dur = (const int*)d_in[0];

    // out is [B, M, T] float32; derive M from out_size.
    const int M = out_size / (B_SZ * T_SZ);

    // Resolve the device-global scratch address is implicit (static symbol).
    build_f2t_kernel<<<B_SZ, T_SZ>>>(dur, M);

    const long long n4 = (long long)out_size / 4;   // T=512 divisible by 4
    const int threads = 256;
    const long long blocks = (n4 + threads - 1) / threads;
    write_align_kernel<<<(unsigned)blocks, threads>>>((float4*)d_out, n4);
}